// round 8
// baseline (speedup 1.0000x reference)
#include <cuda_runtime.h>
#include <cuda_bf16.h>
#include <cstdint>

// ---------------------------------------------------------------------------
// HeteroEdgePromptPlus — folded formulation.
//   logits[e,k] = srcLogits[src(e),k] + dstLogits[dst(e),k]   (bias folded)
//   b = softmax(leaky_relu(logits)) ; out[e] = b @ A
// Edge phase: ONE warp-specialized kernel. 3 producer warps (gather+softmax
// -> smem ring, mbarrier handshake), 5 consumer warps (A-in-regs stream MM).
// ---------------------------------------------------------------------------

#define MAXN 50000
typedef unsigned long long ull;

__device__ float g_Mp[48 * 256];
__device__ float g_cp[48];
__device__ float g_Ma[16 * 128];
__device__ float g_ca[16];
__device__ float g_paperL[(size_t)MAXN * 48];
__device__ float g_authorL[(size_t)MAXN * 16];

// ---- f32x2 packed helpers (Blackwell) -------------------------------------
__device__ __forceinline__ ull pk2(float x, float y) {
    ull r;
    asm("mov.b64 %0, {%1, %2};" : "=l"(r) : "f"(x), "f"(y));
    return r;
}
__device__ __forceinline__ void upk(ull v, float& x, float& y) {
    asm("mov.b64 {%0, %1}, %2;" : "=f"(x), "=f"(y) : "l"(v));
}
__device__ __forceinline__ void fma2(ull& d, ull a, ull b) {
    asm("fma.rn.f32x2 %0, %1, %2, %0;" : "+l"(d) : "l"(a), "l"(b));
}
__device__ __forceinline__ void st4(float* p, ull a, ull b) {
    float x, y, z, w;
    upk(a, x, y);
    upk(b, z, w);
    *reinterpret_cast<float4*>(p) = make_float4(x, y, z, w);
}

// ---- mbarrier helpers ------------------------------------------------------
__device__ __forceinline__ uint32_t smem_u32(const void* p) {
    uint32_t a;
    asm("{ .reg .u64 t; cvta.to.shared.u64 t, %1; cvt.u32.u64 %0, t; }"
        : "=r"(a) : "l"(p));
    return a;
}
__device__ __forceinline__ void mbar_init(uint32_t a, uint32_t cnt) {
    asm volatile("mbarrier.init.shared.b64 [%0], %1;" :: "r"(a), "r"(cnt)
                 : "memory");
}
__device__ __forceinline__ void mbar_arrive(uint32_t a) {
    asm volatile("mbarrier.arrive.shared.b64 _, [%0];" :: "r"(a) : "memory");
}
__device__ __forceinline__ void mbar_wait(uint32_t a, uint32_t parity) {
    asm volatile(
        "{\n\t"
        ".reg .pred P;\n\t"
        "WAIT_%=:\n\t"
        "mbarrier.try_wait.parity.acquire.cta.shared::cta.b64 P, [%0], %1, 0x989680;\n\t"
        "@P bra.uni DONE_%=;\n\t"
        "bra.uni WAIT_%=;\n\t"
        "DONE_%=:\n\t"
        "}" :: "r"(a), "r"(parity) : "memory");
}

// ---------------------------------------------------------------------------
// Kernel 1: fold weights. grid = (64, 4): x = output row, y = p-chunk of 32.
// ---------------------------------------------------------------------------
__global__ void fold_kernel(const float* __restrict__ Wp_p,
                            const float* __restrict__ bp_p,
                            const float* __restrict__ Wp_a,
                            const float* __restrict__ bp_a,
                            const float* __restrict__ Ws_w,
                            const float* __restrict__ bs_w,
                            const float* __restrict__ Ws_c,
                            const float* __restrict__ bs_c) {
    const int b = blockIdx.x, t = threadIdx.x;
    const int pBeg = blockIdx.y * 32, pEnd = pBeg + 32;
    if (b < 48) {
        int k = b & 15, grp = b >> 4;
        const float* wrow = (grp == 0) ? (Ws_w + k * 256 + 128)
                          : (grp == 1) ? (Ws_c + k * 256)
                                       : (Ws_c + k * 256 + 128);
        float a0 = 0.f, a1 = 0.f, a2 = 0.f, a3 = 0.f;
        #pragma unroll
        for (int p = pBeg; p < pEnd; p += 4) {
            a0 = fmaf(__ldg(&wrow[p + 0]), __ldg(&Wp_p[(p + 0) * 256 + t]), a0);
            a1 = fmaf(__ldg(&wrow[p + 1]), __ldg(&Wp_p[(p + 1) * 256 + t]), a1);
            a2 = fmaf(__ldg(&wrow[p + 2]), __ldg(&Wp_p[(p + 2) * 256 + t]), a2);
            a3 = fmaf(__ldg(&wrow[p + 3]), __ldg(&Wp_p[(p + 3) * 256 + t]), a3);
        }
        atomicAdd(&g_Mp[b * 256 + t], (a0 + a1) + (a2 + a3));
        if (t == 0) {
            float c0 = (blockIdx.y == 0)
                           ? ((grp == 0) ? bs_w[k] : (grp == 2) ? bs_c[k] : 0.f)
                           : 0.f;
            float c1 = 0.f, c2 = 0.f, c3 = 0.f;
            #pragma unroll
            for (int p = pBeg; p < pEnd; p += 4) {
                c0 = fmaf(wrow[p + 0], bp_p[p + 0], c0);
                c1 = fmaf(wrow[p + 1], bp_p[p + 1], c1);
                c2 = fmaf(wrow[p + 2], bp_p[p + 2], c2);
                c3 = fmaf(wrow[p + 3], bp_p[p + 3], c3);
            }
            atomicAdd(&g_cp[b], (c0 + c1) + (c2 + c3));
        }
    } else {
        int k = b - 48;
        if (t < 128) {
            const float* wrow = Ws_w + k * 256;  // src half -> author
            float a0 = 0.f, a1 = 0.f, a2 = 0.f, a3 = 0.f;
            #pragma unroll
            for (int p = pBeg; p < pEnd; p += 4) {
                a0 = fmaf(__ldg(&wrow[p + 0]), __ldg(&Wp_a[(p + 0) * 128 + t]), a0);
                a1 = fmaf(__ldg(&wrow[p + 1]), __ldg(&Wp_a[(p + 1) * 128 + t]), a1);
                a2 = fmaf(__ldg(&wrow[p + 2]), __ldg(&Wp_a[(p + 2) * 128 + t]), a2);
                a3 = fmaf(__ldg(&wrow[p + 3]), __ldg(&Wp_a[(p + 3) * 128 + t]), a3);
            }
            atomicAdd(&g_Ma[k * 128 + t], (a0 + a1) + (a2 + a3));
            if (t == 0) {
                float c0 = 0.f, c1 = 0.f, c2 = 0.f, c3 = 0.f;
                #pragma unroll
                for (int p = pBeg; p < pEnd; p += 4) {
                    c0 = fmaf(wrow[p + 0], bp_a[p + 0], c0);
                    c1 = fmaf(wrow[p + 1], bp_a[p + 1], c1);
                    c2 = fmaf(wrow[p + 2], bp_a[p + 2], c2);
                    c3 = fmaf(wrow[p + 3], bp_a[p + 3], c3);
                }
                atomicAdd(&g_ca[k], (c0 + c1) + (c2 + c3));
            }
        }
    }
}

// ---------------------------------------------------------------------------
// Kernel 2: node logits  out[N,KOUT] = X[N,KDIM] @ M[KOUT,KDIM].T + c
// ---------------------------------------------------------------------------
template <int KDIM, int KOUT, int OPT>
__device__ __forceinline__ void node_body(const float* __restrict__ X,
                                          const float* __restrict__ M,
                                          const float* __restrict__ c,
                                          float* __restrict__ out, int N,
                                          int blk, float* Xs, float* Ms) {
    constexpr int KT = 32;
    const int t = threadIdx.x;
    const int n0 = blk * 128;
    const int ng = t & 63;
    const int og = t >> 6;

    ull acc0[OPT / 2], acc1[OPT / 2];
    #pragma unroll
    for (int i = 0; i < OPT / 2; i++) { acc0[i] = 0ull; acc1[i] = 0ull; }

    const int sn = n0 + (t >> 1);
    const int sj = (t & 1) * 16;
    const bool vs = sn < N;
    const float* xrow = X + (size_t)(vs ? sn : (N - 1)) * KDIM;

    for (int j0 = 0; j0 < KDIM; j0 += KT) {
        #pragma unroll
        for (int q = 0; q < 4; q++) {
            float4 v = vs ? *reinterpret_cast<const float4*>(xrow + j0 + sj + 4 * q)
                          : make_float4(0.f, 0.f, 0.f, 0.f);
            int jj = sj + 4 * q;
            Xs[(jj + 0) * 128 + (t >> 1)] = v.x;
            Xs[(jj + 1) * 128 + (t >> 1)] = v.y;
            Xs[(jj + 2) * 128 + (t >> 1)] = v.z;
            Xs[(jj + 3) * 128 + (t >> 1)] = v.w;
        }
        #pragma unroll
        for (int idx = t; idx < KT * KOUT; idx += 256) {
            int j = idx / KOUT, k = idx - j * KOUT;
            Ms[j * KOUT + k] = M[k * KDIM + j0 + j];
        }
        __syncthreads();
        #pragma unroll
        for (int j = 0; j < KT; j++) {
            float2 xv = *reinterpret_cast<const float2*>(&Xs[j * 128 + 2 * ng]);
            ull xx = pk2(xv.x, xv.x);
            ull yy = pk2(xv.y, xv.y);
            #pragma unroll
            for (int cp = 0; cp < OPT / 2; cp++) {
                ull m2 = *reinterpret_cast<const ull*>(&Ms[j * KOUT + og * OPT + 2 * cp]);
                fma2(acc0[cp], xx, m2);
                fma2(acc1[cp], yy, m2);
            }
        }
        __syncthreads();
    }

    float r0[OPT], r1[OPT];
    #pragma unroll
    for (int cp = 0; cp < OPT / 2; cp++) {
        upk(acc0[cp], r0[2 * cp], r0[2 * cp + 1]);
        upk(acc1[cp], r1[2 * cp], r1[2 * cp + 1]);
    }
    #pragma unroll
    for (int cc = 0; cc < OPT; cc++) {
        float bias = __ldg(&c[og * OPT + cc]);
        r0[cc] += bias;
        r1[cc] += bias;
    }
    const int nA = n0 + 2 * ng, nB = nA + 1;
    if (nA < N) {
        #pragma unroll
        for (int v = 0; v < OPT / 4; v++)
            *reinterpret_cast<float4*>(&out[(size_t)nA * KOUT + og * OPT + 4 * v]) =
                make_float4(r0[4 * v], r0[4 * v + 1], r0[4 * v + 2], r0[4 * v + 3]);
    }
    if (nB < N) {
        #pragma unroll
        for (int v = 0; v < OPT / 4; v++)
            *reinterpret_cast<float4*>(&out[(size_t)nB * KOUT + og * OPT + 4 * v]) =
                make_float4(r1[4 * v], r1[4 * v + 1], r1[4 * v + 2], r1[4 * v + 3]);
    }
}

__global__ void __launch_bounds__(256)
node_kernel(const float* __restrict__ xp, const float* __restrict__ xa,
            const float* __restrict__ Mp, const float* __restrict__ cp,
            const float* __restrict__ Ma, const float* __restrict__ ca,
            float* __restrict__ pL, float* __restrict__ aL,
            int Np, int Na, int npBlocks) {
    __shared__ float Xs[32 * 128];
    __shared__ float Ms[32 * 48];
    if ((int)blockIdx.x < npBlocks)
        node_body<256, 48, 12>(xp, Mp, cp, pL, Np, blockIdx.x, Xs, Ms);
    else
        node_body<128, 16, 4>(xa, Ma, ca, aL, Na, blockIdx.x - npBlocks, Xs, Ms);
}

// ---------------------------------------------------------------------------
// Kernel 3: warp-specialized fused edge kernel.
// Batch = 4 edges. 15-slot smem ring. Warps 0-2 produce (slot ≡ t mod 3),
// warps 3-7 consume (slot ≡ t mod 5). Per-slot parity = (t/15)&1.
// ---------------------------------------------------------------------------
#define NSLOT 15

__global__ void __launch_bounds__(256, 2)
edge_ws_kernel(const int* __restrict__ eiW, const int* __restrict__ eiC, int E,
               const float* __restrict__ aL, const float* __restrict__ pL,
               const float* __restrict__ A_w, const float* __restrict__ A_c,
               float* __restrict__ out, int nbHalf) {
    __shared__ __align__(16) float2 bslots[NSLOT][64];  // 4 edges x 16 {b,b}
    __shared__ ull mbar[2 * NSLOT];                     // full[15], empty[15]

    const bool isW = (int)blockIdx.x < nbHalf;
    const int bid = isW ? blockIdx.x : blockIdx.x - nbHalf;
    const int* ei = isW ? eiW : eiC;
    const float* srcL = isW ? aL : (pL + 16);
    const int sStride = isW ? 16 : 48;
    const float* dstL = isW ? pL : (pL + 32);
    const float* A = isW ? A_w : A_c;
    float* o = isW ? out : out + (size_t)E * 128;

    const int tid = threadIdx.x;
    const int lane = tid & 31;
    const int w = tid >> 5;

    const uint32_t mb0 = smem_u32(&mbar[0]);
    if (tid < 2 * NSLOT) mbar_init(mb0 + 8 * tid, 1);
    __syncthreads();
    #define FULLB(s)  (mb0 + 8 * (s))
    #define EMPTYB(s) (mb0 + 8 * (NSLOT + (s)))

    const int totB = (E + 3) >> 2;                       // batches of 4 edges
    const int nb = (totB - bid + nbHalf - 1) / nbHalf;   // this block's batches

    if (w < 3) {
        // ------------------ producer: gather + softmax ---------------------
        const int k16 = lane & 15;
        const int half = lane >> 4;
        for (int t = w; t < nb; t += 3) {
            const int g = bid + t * nbHalf;              // global batch
            // gathers first (latency flies under the empty-wait)
            float lg[2];
            #pragma unroll
            for (int u = 0; u < 2; u++) {
                int e = min(4 * g + 2 * u + half, E - 1);
                int s = __ldg(&ei[e]);
                int d = __ldg(&ei[E + e]);
                float l = __ldg(&srcL[(size_t)s * sStride + k16]) +
                          __ldg(&dstL[(size_t)d * 48 + k16]);
                lg[u] = fmaxf(l, 0.01f * l);             // leaky_relu
            }
            const int slot = t % NSLOT;
            const uint32_t par = ((uint32_t)(t / NSLOT) & 1u) ^ 1u;
            mbar_wait(EMPTYB(slot), par);

            // no-max softmax (logits bounded; fp32 headroom is huge)
            float ex0 = __expf(lg[0]), ex1 = __expf(lg[1]);
            float s0 = ex0, s1 = ex1;
            #pragma unroll
            for (int m = 8; m; m >>= 1) {
                s0 += __shfl_xor_sync(0xffffffffu, s0, m, 16);
                s1 += __shfl_xor_sync(0xffffffffu, s1, m, 16);
            }
            float b0 = __fdividef(ex0, s0);
            float b1 = __fdividef(ex1, s1);
            bslots[slot][lane]      = make_float2(b0, b0);
            bslots[slot][32 + lane] = make_float2(b1, b1);
            __syncwarp();
            if (lane == 0) mbar_arrive(FULLB(slot));
        }
    } else {
        // ------------------ consumer: out = b @ A --------------------------
        // A -> regs: lane owns output cols [4*lane, 4*lane+4) for all 16 k.
        ull aLr[16], aHr[16];
        #pragma unroll
        for (int k = 0; k < 16; k++) {
            float4 v = reinterpret_cast<const float4*>(A)[k * 32 + lane];
            aLr[k] = pk2(v.x, v.y);
            aHr[k] = pk2(v.z, v.w);
        }
        const int c = w - 3;
        for (int t = c; t < nb; t += 5) {
            const int g = bid + t * nbHalf;
            const int slot = t % NSLOT;
            const uint32_t par = (uint32_t)(t / NSLOT) & 1u;
            mbar_wait(FULLB(slot), par);

            #pragma unroll
            for (int v = 0; v < 4; v++) {
                const ulonglong2* bq = reinterpret_cast<const ulonglong2*>(
                    &bslots[slot][(v >> 1) * 32 + (v & 1) * 16]);
                ull accL = 0ull, accH = 0ull;
                #pragma unroll
                for (int k2 = 0; k2 < 8; k2++) {
                    ulonglong2 q = bq[k2];
                    fma2(accL, q.x, aLr[2 * k2]);
                    fma2(accH, q.x, aHr[2 * k2]);
                    fma2(accL, q.y, aLr[2 * k2 + 1]);
                    fma2(accH, q.y, aHr[2 * k2 + 1]);
                }
                int e = 4 * g + v;
                if (e < E)
                    st4(o + (size_t)e * 128 + 4 * lane, accL, accH);
            }
            __syncwarp();
            if (lane == 0) mbar_arrive(EMPTYB(slot));
        }
    }
    #undef FULLB
    #undef EMPTYB
}

// ---------------------------------------------------------------------------
extern "C" void kernel_launch(void* const* d_in, const int* in_sizes, int n_in,
                              void* d_out, int out_size) {
    const float* x_paper   = (const float*)d_in[0];
    const float* x_author  = (const float*)d_in[1];
    const float* Wp_paper  = (const float*)d_in[2];
    const float* bp_paper  = (const float*)d_in[3];
    const float* Wp_author = (const float*)d_in[4];
    const float* bp_author = (const float*)d_in[5];
    const float* Ws_writes = (const float*)d_in[6];
    const float* bs_writes = (const float*)d_in[7];
    const float* A_writes  = (const float*)d_in[8];
    const float* Ws_cites  = (const float*)d_in[9];
    const float* bs_cites  = (const float*)d_in[10];
    const float* A_cites   = (const float*)d_in[11];
    const int*   ei_writes = (const int*)d_in[12];
    const int*   ei_cites  = (const int*)d_in[13];
    float* out = (float*)d_out;

    const int Np = in_sizes[0] / 256;
    const int Na = in_sizes[1] / 128;
    const int E  = in_sizes[12] / 2;

    float *Mp, *cp, *Ma, *ca, *pL, *aL;
    cudaGetSymbolAddress((void**)&Mp, g_Mp);
    cudaGetSymbolAddress((void**)&cp, g_cp);
    cudaGetSymbolAddress((void**)&Ma, g_Ma);
    cudaGetSymbolAddress((void**)&ca, g_ca);
    cudaGetSymbolAddress((void**)&pL, g_paperL);
    cudaGetSymbolAddress((void**)&aL, g_authorL);

    cudaMemsetAsync(Mp, 0, 48 * 256 * sizeof(float));
    cudaMemsetAsync(cp, 0, 48 * sizeof(float));
    cudaMemsetAsync(Ma, 0, 16 * 128 * sizeof(float));
    cudaMemsetAsync(ca, 0, 16 * sizeof(float));

    fold_kernel<<<dim3(64, 4), 256>>>(Wp_paper, bp_paper, Wp_author, bp_author,
                                      Ws_writes, bs_writes, Ws_cites, bs_cites);

    const int npB = (Np + 127) / 128;
    const int naB = (Na + 127) / 128;
    node_kernel<<<npB + naB, 256>>>(x_paper, x_author, Mp, cp, Ma, ca,
                                    pL, aL, Np, Na, npB);

    const int nbHalf = 148;  // 2 CTAs/SM (one per edge type) x 148 SMs
    edge_ws_kernel<<<2 * nbHalf, 256>>>(ei_writes, ei_cites, E, aL, pL,
                                        A_writes, A_cites, out, nbHalf);
}

// round 9
// speedup vs baseline: 2.0001x; 2.0001x over previous
#include <cuda_runtime.h>
#include <cuda_bf16.h>
#include <cstdint>

// ---------------------------------------------------------------------------
// HeteroEdgePromptPlus — folded formulation.
//   logits[e,k] = srcLogits[src(e),k] + dstLogits[dst(e),k]   (bias folded)
//   b = softmax(leaky_relu(logits)) ; out[e] = b @ A
// Fused edge kernel (round-7 structure), 4-pair (8-edge) pipelined batches.
// ---------------------------------------------------------------------------

#define MAXN 50000
typedef unsigned long long ull;

__device__ float g_Mp[48 * 256];
__device__ float g_cp[48];
__device__ float g_Ma[16 * 128];
__device__ float g_ca[16];
__device__ float g_paperL[(size_t)MAXN * 48];
__device__ float g_authorL[(size_t)MAXN * 16];

// ---- f32x2 packed helpers (Blackwell) -------------------------------------
__device__ __forceinline__ ull pk2(float x, float y) {
    ull r;
    asm("mov.b64 %0, {%1, %2};" : "=l"(r) : "f"(x), "f"(y));
    return r;
}
__device__ __forceinline__ void upk(ull v, float& x, float& y) {
    asm("mov.b64 {%0, %1}, %2;" : "=f"(x), "=f"(y) : "l"(v));
}
__device__ __forceinline__ void fma2(ull& d, ull a, ull b) {
    asm("fma.rn.f32x2 %0, %1, %2, %0;" : "+l"(d) : "l"(a), "l"(b));
}
__device__ __forceinline__ void st4(float* p, ull a, ull b) {
    float x, y, z, w;
    upk(a, x, y);
    upk(b, z, w);
    *reinterpret_cast<float4*>(p) = make_float4(x, y, z, w);
}

// ---------------------------------------------------------------------------
// Kernel 1: fold weights. grid = (64, 4): x = output row, y = p-chunk of 32.
// ---------------------------------------------------------------------------
__global__ void fold_kernel(const float* __restrict__ Wp_p,
                            const float* __restrict__ bp_p,
                            const float* __restrict__ Wp_a,
                            const float* __restrict__ bp_a,
                            const float* __restrict__ Ws_w,
                            const float* __restrict__ bs_w,
                            const float* __restrict__ Ws_c,
                            const float* __restrict__ bs_c) {
    const int b = blockIdx.x, t = threadIdx.x;
    const int pBeg = blockIdx.y * 32, pEnd = pBeg + 32;
    if (b < 48) {
        int k = b & 15, grp = b >> 4;
        const float* wrow = (grp == 0) ? (Ws_w + k * 256 + 128)
                          : (grp == 1) ? (Ws_c + k * 256)
                                       : (Ws_c + k * 256 + 128);
        float a0 = 0.f, a1 = 0.f, a2 = 0.f, a3 = 0.f;
        #pragma unroll
        for (int p = pBeg; p < pEnd; p += 4) {
            a0 = fmaf(__ldg(&wrow[p + 0]), __ldg(&Wp_p[(p + 0) * 256 + t]), a0);
            a1 = fmaf(__ldg(&wrow[p + 1]), __ldg(&Wp_p[(p + 1) * 256 + t]), a1);
            a2 = fmaf(__ldg(&wrow[p + 2]), __ldg(&Wp_p[(p + 2) * 256 + t]), a2);
            a3 = fmaf(__ldg(&wrow[p + 3]), __ldg(&Wp_p[(p + 3) * 256 + t]), a3);
        }
        atomicAdd(&g_Mp[b * 256 + t], (a0 + a1) + (a2 + a3));
        if (t == 0) {
            float c0 = (blockIdx.y == 0)
                           ? ((grp == 0) ? bs_w[k] : (grp == 2) ? bs_c[k] : 0.f)
                           : 0.f;
            float c1 = 0.f, c2 = 0.f, c3 = 0.f;
            #pragma unroll
            for (int p = pBeg; p < pEnd; p += 4) {
                c0 = fmaf(wrow[p + 0], bp_p[p + 0], c0);
                c1 = fmaf(wrow[p + 1], bp_p[p + 1], c1);
                c2 = fmaf(wrow[p + 2], bp_p[p + 2], c2);
                c3 = fmaf(wrow[p + 3], bp_p[p + 3], c3);
            }
            atomicAdd(&g_cp[b], (c0 + c1) + (c2 + c3));
        }
    } else {
        int k = b - 48;
        if (t < 128) {
            const float* wrow = Ws_w + k * 256;  // src half -> author
            float a0 = 0.f, a1 = 0.f, a2 = 0.f, a3 = 0.f;
            #pragma unroll
            for (int p = pBeg; p < pEnd; p += 4) {
                a0 = fmaf(__ldg(&wrow[p + 0]), __ldg(&Wp_a[(p + 0) * 128 + t]), a0);
                a1 = fmaf(__ldg(&wrow[p + 1]), __ldg(&Wp_a[(p + 1) * 128 + t]), a1);
                a2 = fmaf(__ldg(&wrow[p + 2]), __ldg(&Wp_a[(p + 2) * 128 + t]), a2);
                a3 = fmaf(__ldg(&wrow[p + 3]), __ldg(&Wp_a[(p + 3) * 128 + t]), a3);
            }
            atomicAdd(&g_Ma[k * 128 + t], (a0 + a1) + (a2 + a3));
            if (t == 0) {
                float c0 = 0.f, c1 = 0.f, c2 = 0.f, c3 = 0.f;
                #pragma unroll
                for (int p = pBeg; p < pEnd; p += 4) {
                    c0 = fmaf(wrow[p + 0], bp_a[p + 0], c0);
                    c1 = fmaf(wrow[p + 1], bp_a[p + 1], c1);
                    c2 = fmaf(wrow[p + 2], bp_a[p + 2], c2);
                    c3 = fmaf(wrow[p + 3], bp_a[p + 3], c3);
                }
                atomicAdd(&g_ca[k], (c0 + c1) + (c2 + c3));
            }
        }
    }
}

// ---------------------------------------------------------------------------
// Kernel 2: node logits  out[N,KOUT] = X[N,KDIM] @ M[KOUT,KDIM].T + c
// ---------------------------------------------------------------------------
template <int KDIM, int KOUT, int OPT>
__device__ __forceinline__ void node_body(const float* __restrict__ X,
                                          const float* __restrict__ M,
                                          const float* __restrict__ c,
                                          float* __restrict__ out, int N,
                                          int blk, float* Xs, float* Ms) {
    constexpr int KT = 32;
    const int t = threadIdx.x;
    const int n0 = blk * 128;
    const int ng = t & 63;
    const int og = t >> 6;

    ull acc0[OPT / 2], acc1[OPT / 2];
    #pragma unroll
    for (int i = 0; i < OPT / 2; i++) { acc0[i] = 0ull; acc1[i] = 0ull; }

    const int sn = n0 + (t >> 1);
    const int sj = (t & 1) * 16;
    const bool vs = sn < N;
    const float* xrow = X + (size_t)(vs ? sn : (N - 1)) * KDIM;

    for (int j0 = 0; j0 < KDIM; j0 += KT) {
        #pragma unroll
        for (int q = 0; q < 4; q++) {
            float4 v = vs ? *reinterpret_cast<const float4*>(xrow + j0 + sj + 4 * q)
                          : make_float4(0.f, 0.f, 0.f, 0.f);
            int jj = sj + 4 * q;
            Xs[(jj + 0) * 128 + (t >> 1)] = v.x;
            Xs[(jj + 1) * 128 + (t >> 1)] = v.y;
            Xs[(jj + 2) * 128 + (t >> 1)] = v.z;
            Xs[(jj + 3) * 128 + (t >> 1)] = v.w;
        }
        #pragma unroll
        for (int idx = t; idx < KT * KOUT; idx += 256) {
            int j = idx / KOUT, k = idx - j * KOUT;
            Ms[j * KOUT + k] = M[k * KDIM + j0 + j];
        }
        __syncthreads();
        #pragma unroll
        for (int j = 0; j < KT; j++) {
            float2 xv = *reinterpret_cast<const float2*>(&Xs[j * 128 + 2 * ng]);
            ull xx = pk2(xv.x, xv.x);
            ull yy = pk2(xv.y, xv.y);
            #pragma unroll
            for (int cp = 0; cp < OPT / 2; cp++) {
                ull m2 = *reinterpret_cast<const ull*>(&Ms[j * KOUT + og * OPT + 2 * cp]);
                fma2(acc0[cp], xx, m2);
                fma2(acc1[cp], yy, m2);
            }
        }
        __syncthreads();
    }

    float r0[OPT], r1[OPT];
    #pragma unroll
    for (int cp = 0; cp < OPT / 2; cp++) {
        upk(acc0[cp], r0[2 * cp], r0[2 * cp + 1]);
        upk(acc1[cp], r1[2 * cp], r1[2 * cp + 1]);
    }
    #pragma unroll
    for (int cc = 0; cc < OPT; cc++) {
        float bias = __ldg(&c[og * OPT + cc]);
        r0[cc] += bias;
        r1[cc] += bias;
    }
    const int nA = n0 + 2 * ng, nB = nA + 1;
    if (nA < N) {
        #pragma unroll
        for (int v = 0; v < OPT / 4; v++)
            *reinterpret_cast<float4*>(&out[(size_t)nA * KOUT + og * OPT + 4 * v]) =
                make_float4(r0[4 * v], r0[4 * v + 1], r0[4 * v + 2], r0[4 * v + 3]);
    }
    if (nB < N) {
        #pragma unroll
        for (int v = 0; v < OPT / 4; v++)
            *reinterpret_cast<float4*>(&out[(size_t)nB * KOUT + og * OPT + 4 * v]) =
                make_float4(r1[4 * v], r1[4 * v + 1], r1[4 * v + 2], r1[4 * v + 3]);
    }
}

__global__ void __launch_bounds__(256)
node_kernel(const float* __restrict__ xp, const float* __restrict__ xa,
            const float* __restrict__ Mp, const float* __restrict__ cp,
            const float* __restrict__ Ma, const float* __restrict__ ca,
            float* __restrict__ pL, float* __restrict__ aL,
            int Np, int Na, int npBlocks) {
    __shared__ float Xs[32 * 128];
    __shared__ float Ms[32 * 48];
    if ((int)blockIdx.x < npBlocks)
        node_body<256, 48, 12>(xp, Mp, cp, pL, Np, blockIdx.x, Xs, Ms);
    else
        node_body<128, 16, 4>(xa, Ma, ca, aL, Na, blockIdx.x - npBlocks, Xs, Ms);
}

// ---------------------------------------------------------------------------
// Kernel 3 (fused, merged edge types): A in regs (4 cols/lane), broadcast
// LDS, STG.128, (256,2). 4 pairs (8 edges) per iteration: softmax chains run
// 4-way ILP'd, next batch's gathers prefetched under the 256-fma2 burst.
// ---------------------------------------------------------------------------
__global__ void __launch_bounds__(256, 2)
edge_fused_kernel(const int* __restrict__ eiW, const int* __restrict__ eiC,
                  int E,
                  const float* __restrict__ aL, const float* __restrict__ pL,
                  const float* __restrict__ A_w, const float* __restrict__ A_c,
                  float* __restrict__ out, int nbHalf) {
    __shared__ __align__(16) float2 bsh[8][4][32];

    const bool isW = (int)blockIdx.x < nbHalf;
    const int bid = isW ? blockIdx.x : blockIdx.x - nbHalf;
    const int* ei = isW ? eiW : eiC;
    const float* srcL = isW ? aL : (pL + 16);
    const int sStride = isW ? 16 : 48;
    const float* dstL = isW ? pL : (pL + 32);
    const float* A = isW ? A_w : A_c;
    float* o = isW ? out : out + (size_t)E * 128;

    const int lane = threadIdx.x & 31;
    const int w = threadIdx.x >> 5;
    const int k16 = lane & 15;
    const int half = lane >> 4;

    // A preload: lane owns output columns [4*lane, 4*lane+4) for all 16 k.
    ull aLr[16], aHr[16];
    #pragma unroll
    for (int k = 0; k < 16; k++) {
        float4 v = reinterpret_cast<const float4*>(A)[k * 32 + lane];
        aLr[k] = pk2(v.x, v.y);
        aHr[k] = pk2(v.z, v.w);
    }

    const int pairs = E >> 1;              // E even
    const int gw = bid * 8 + w;
    const int step = nbHalf * 8 * 4;       // pairs consumed per iter, all warps

    int p0 = gw * 4;
    if (p0 >= pairs) return;

    // prologue: gather + leaky-relu logits for first batch (4 pairs)
    float lg[4];
    #pragma unroll
    for (int u = 0; u < 4; u++) {
        int e = min(2 * (p0 + u) + half, E - 1);
        int s = __ldg(&ei[e]);
        int d = __ldg(&ei[E + e]);
        float l = __ldg(&srcL[(size_t)s * sStride + k16]) +
                  __ldg(&dstL[(size_t)d * 48 + k16]);
        lg[u] = fmaxf(l, 0.01f * l);
    }

    for (; p0 < pairs; p0 += step) {
        // softmax (no max-subtraction: logits bounded, fp32 headroom is huge)
        float ex[4], sm[4];
        #pragma unroll
        for (int u = 0; u < 4; u++) {
            ex[u] = __expf(lg[u]);
            sm[u] = ex[u];
        }
        #pragma unroll
        for (int m = 8; m; m >>= 1) {
            #pragma unroll
            for (int u = 0; u < 4; u++)
                sm[u] += __shfl_xor_sync(0xffffffffu, sm[u], m, 16);
        }
        #pragma unroll
        for (int u = 0; u < 4; u++) {
            float b = __fdividef(ex[u], sm[u]);
            bsh[w][u][lane] = make_float2(b, b);
        }

        // prefetch next batch's gathers (fly under the FMA burst below)
        float lgN[4];
        {
            int pn = (p0 + step < pairs) ? (p0 + step) : p0;
            #pragma unroll
            for (int u = 0; u < 4; u++) {
                int e = min(2 * (pn + u) + half, E - 1);
                int s = __ldg(&ei[e]);
                int d = __ldg(&ei[E + e]);
                float l = __ldg(&srcL[(size_t)s * sStride + k16]) +
                          __ldg(&dstL[(size_t)d * 48 + k16]);
                lgN[u] = fmaxf(l, 0.01f * l);
            }
        }
        __syncwarp();

        // matmul epilogue: 8 edges x (8 broadcast LDS.128 + 32 fma2 + STG.128)
        #pragma unroll
        for (int u = 0; u < 4; u++) {
            if (p0 + u < pairs) {
                #pragma unroll
                for (int h = 0; h < 2; h++) {
                    const ulonglong2* bq =
                        reinterpret_cast<const ulonglong2*>(&bsh[w][u][16 * h]);
                    ull accL = 0ull, accH = 0ull;
                    #pragma unroll
                    for (int k2 = 0; k2 < 8; k2++) {
                        ulonglong2 q = bq[k2];
                        fma2(accL, q.x, aLr[2 * k2]);
                        fma2(accH, q.x, aHr[2 * k2]);
                        fma2(accL, q.y, aLr[2 * k2 + 1]);
                        fma2(accH, q.y, aHr[2 * k2 + 1]);
                    }
                    st4(o + (size_t)(2 * (p0 + u) + h) * 128 + 4 * lane,
                        accL, accH);
                }
            }
        }
        __syncwarp();
        #pragma unroll
        for (int u = 0; u < 4; u++) lg[u] = lgN[u];
    }
}

// ---------------------------------------------------------------------------
extern "C" void kernel_launch(void* const* d_in, const int* in_sizes, int n_in,
                              void* d_out, int out_size) {
    const float* x_paper   = (const float*)d_in[0];
    const float* x_author  = (const float*)d_in[1];
    const float* Wp_paper  = (const float*)d_in[2];
    const float* bp_paper  = (const float*)d_in[3];
    const float* Wp_author = (const float*)d_in[4];
    const float* bp_author = (const float*)d_in[5];
    const float* Ws_writes = (const float*)d_in[6];
    const float* bs_writes = (const float*)d_in[7];
    const float* A_writes  = (const float*)d_in[8];
    const float* Ws_cites  = (const float*)d_in[9];
    const float* bs_cites  = (const float*)d_in[10];
    const float* A_cites   = (const float*)d_in[11];
    const int*   ei_writes = (const int*)d_in[12];
    const int*   ei_cites  = (const int*)d_in[13];
    float* out = (float*)d_out;

    const int Np = in_sizes[0] / 256;
    const int Na = in_sizes[1] / 128;
    const int E  = in_sizes[12] / 2;

    float *Mp, *cp, *Ma, *ca, *pL, *aL;
    cudaGetSymbolAddress((void**)&Mp, g_Mp);
    cudaGetSymbolAddress((void**)&cp, g_cp);
    cudaGetSymbolAddress((void**)&Ma, g_Ma);
    cudaGetSymbolAddress((void**)&ca, g_ca);
    cudaGetSymbolAddress((void**)&pL, g_paperL);
    cudaGetSymbolAddress((void**)&aL, g_authorL);

    cudaMemsetAsync(Mp, 0, 48 * 256 * sizeof(float));
    cudaMemsetAsync(cp, 0, 48 * sizeof(float));
    cudaMemsetAsync(Ma, 0, 16 * 128 * sizeof(float));
    cudaMemsetAsync(ca, 0, 16 * sizeof(float));

    fold_kernel<<<dim3(64, 4), 256>>>(Wp_paper, bp_paper, Wp_author, bp_author,
                                      Ws_writes, bs_writes, Ws_cites, bs_cites);

    const int npB = (Np + 127) / 128;
    const int naB = (Na + 127) / 128;
    node_kernel<<<npB + naB, 256>>>(x_paper, x_author, Mp, cp, Ma, ca,
                                    pL, aL, Np, Na, npB);

    const int nbHalf = 296;  // 2 CTAs/SM x 148 SMs / 2 edge types
    edge_fused_kernel<<<2 * nbHalf, 256>>>(ei_writes, ei_cites, E, aL, pL,
                                           A_writes, A_cites, out, nbHalf);
}

// round 10
// speedup vs baseline: 2.0357x; 1.0178x over previous
#include <cuda_runtime.h>
#include <cuda_bf16.h>
#include <cstdint>

// ---------------------------------------------------------------------------
// HeteroEdgePromptPlus — folded formulation.
//   logits[e,k] = srcLogits[src(e),k] + dstLogits[dst(e),k]   (bias folded)
//   b = softmax(leaky_relu(logits)) ; out[e] = b @ A
// Fused edge kernel: 3-stage SW pipeline (gathers t+2 | softmax t+1 | MM t).
// ---------------------------------------------------------------------------

#define MAXN 50000
typedef unsigned long long ull;

// fold outputs in ONE buffer (single memset): Mp | Ma | cp | ca
__device__ float g_fold[48 * 256 + 16 * 128 + 48 + 16];
#define G_MP (g_fold)
#define G_MA (g_fold + 12288)
#define G_CP (g_fold + 14336)
#define G_CA (g_fold + 14384)
__device__ float g_paperL[(size_t)MAXN * 48];
__device__ float g_authorL[(size_t)MAXN * 16];

// ---- f32x2 packed helpers (Blackwell) -------------------------------------
__device__ __forceinline__ ull pk2(float x, float y) {
    ull r;
    asm("mov.b64 %0, {%1, %2};" : "=l"(r) : "f"(x), "f"(y));
    return r;
}
__device__ __forceinline__ void upk(ull v, float& x, float& y) {
    asm("mov.b64 {%0, %1}, %2;" : "=f"(x), "=f"(y) : "l"(v));
}
__device__ __forceinline__ void fma2(ull& d, ull a, ull b) {
    asm("fma.rn.f32x2 %0, %1, %2, %0;" : "+l"(d) : "l"(a), "l"(b));
}
__device__ __forceinline__ void st4cs(float* p, ull a, ull b) {
    float x, y, z, w;
    upk(a, x, y);
    upk(b, z, w);
    asm volatile("st.global.cs.v4.f32 [%0], {%1, %2, %3, %4};"
                 :: "l"(p), "f"(x), "f"(y), "f"(z), "f"(w) : "memory");
}

// ---------------------------------------------------------------------------
// Kernel 1: fold weights. grid = (64, 4): x = output row, y = p-chunk of 32.
// ---------------------------------------------------------------------------
__global__ void fold_kernel(const float* __restrict__ Wp_p,
                            const float* __restrict__ bp_p,
                            const float* __restrict__ Wp_a,
                            const float* __restrict__ bp_a,
                            const float* __restrict__ Ws_w,
                            const float* __restrict__ bs_w,
                            const float* __restrict__ Ws_c,
                            const float* __restrict__ bs_c) {
    const int b = blockIdx.x, t = threadIdx.x;
    const int pBeg = blockIdx.y * 32, pEnd = pBeg + 32;
    if (b < 48) {
        int k = b & 15, grp = b >> 4;
        const float* wrow = (grp == 0) ? (Ws_w + k * 256 + 128)
                          : (grp == 1) ? (Ws_c + k * 256)
                                       : (Ws_c + k * 256 + 128);
        float a0 = 0.f, a1 = 0.f, a2 = 0.f, a3 = 0.f;
        #pragma unroll
        for (int p = pBeg; p < pEnd; p += 4) {
            a0 = fmaf(__ldg(&wrow[p + 0]), __ldg(&Wp_p[(p + 0) * 256 + t]), a0);
            a1 = fmaf(__ldg(&wrow[p + 1]), __ldg(&Wp_p[(p + 1) * 256 + t]), a1);
            a2 = fmaf(__ldg(&wrow[p + 2]), __ldg(&Wp_p[(p + 2) * 256 + t]), a2);
            a3 = fmaf(__ldg(&wrow[p + 3]), __ldg(&Wp_p[(p + 3) * 256 + t]), a3);
        }
        atomicAdd(&G_MP[b * 256 + t], (a0 + a1) + (a2 + a3));
        if (t == 0) {
            float c0 = (blockIdx.y == 0)
                           ? ((grp == 0) ? bs_w[k] : (grp == 2) ? bs_c[k] : 0.f)
                           : 0.f;
            float c1 = 0.f, c2 = 0.f, c3 = 0.f;
            #pragma unroll
            for (int p = pBeg; p < pEnd; p += 4) {
                c0 = fmaf(wrow[p + 0], bp_p[p + 0], c0);
                c1 = fmaf(wrow[p + 1], bp_p[p + 1], c1);
                c2 = fmaf(wrow[p + 2], bp_p[p + 2], c2);
                c3 = fmaf(wrow[p + 3], bp_p[p + 3], c3);
            }
            atomicAdd(&G_CP[b], (c0 + c1) + (c2 + c3));
        }
    } else {
        int k = b - 48;
        if (t < 128) {
            const float* wrow = Ws_w + k * 256;  // src half -> author
            float a0 = 0.f, a1 = 0.f, a2 = 0.f, a3 = 0.f;
            #pragma unroll
            for (int p = pBeg; p < pEnd; p += 4) {
                a0 = fmaf(__ldg(&wrow[p + 0]), __ldg(&Wp_a[(p + 0) * 128 + t]), a0);
                a1 = fmaf(__ldg(&wrow[p + 1]), __ldg(&Wp_a[(p + 1) * 128 + t]), a1);
                a2 = fmaf(__ldg(&wrow[p + 2]), __ldg(&Wp_a[(p + 2) * 128 + t]), a2);
                a3 = fmaf(__ldg(&wrow[p + 3]), __ldg(&Wp_a[(p + 3) * 128 + t]), a3);
            }
            atomicAdd(&G_MA[k * 128 + t], (a0 + a1) + (a2 + a3));
            if (t == 0) {
                float c0 = 0.f, c1 = 0.f, c2 = 0.f, c3 = 0.f;
                #pragma unroll
                for (int p = pBeg; p < pEnd; p += 4) {
                    c0 = fmaf(wrow[p + 0], bp_a[p + 0], c0);
                    c1 = fmaf(wrow[p + 1], bp_a[p + 1], c1);
                    c2 = fmaf(wrow[p + 2], bp_a[p + 2], c2);
                    c3 = fmaf(wrow[p + 3], bp_a[p + 3], c3);
                }
                atomicAdd(&G_CA[k], (c0 + c1) + (c2 + c3));
            }
        }
    }
}

// ---------------------------------------------------------------------------
// Kernel 2: node logits  out[N,KOUT] = X[N,KDIM] @ M[KOUT,KDIM].T + c
// ---------------------------------------------------------------------------
template <int KDIM, int KOUT, int OPT>
__device__ __forceinline__ void node_body(const float* __restrict__ X,
                                          const float* __restrict__ M,
                                          const float* __restrict__ c,
                                          float* __restrict__ out, int N,
                                          int blk, float* Xs, float* Ms) {
    constexpr int KT = 32;
    const int t = threadIdx.x;
    const int n0 = blk * 128;
    const int ng = t & 63;
    const int og = t >> 6;

    ull acc0[OPT / 2], acc1[OPT / 2];
    #pragma unroll
    for (int i = 0; i < OPT / 2; i++) { acc0[i] = 0ull; acc1[i] = 0ull; }

    const int sn = n0 + (t >> 1);
    const int sj = (t & 1) * 16;
    const bool vs = sn < N;
    const float* xrow = X + (size_t)(vs ? sn : (N - 1)) * KDIM;

    for (int j0 = 0; j0 < KDIM; j0 += KT) {
        #pragma unroll
        for (int q = 0; q < 4; q++) {
            float4 v = vs ? *reinterpret_cast<const float4*>(xrow + j0 + sj + 4 * q)
                          : make_float4(0.f, 0.f, 0.f, 0.f);
            int jj = sj + 4 * q;
            Xs[(jj + 0) * 128 + (t >> 1)] = v.x;
            Xs[(jj + 1) * 128 + (t >> 1)] = v.y;
            Xs[(jj + 2) * 128 + (t >> 1)] = v.z;
            Xs[(jj + 3) * 128 + (t >> 1)] = v.w;
        }
        #pragma unroll
        for (int idx = t; idx < KT * KOUT; idx += 256) {
            int j = idx / KOUT, k = idx - j * KOUT;
            Ms[j * KOUT + k] = M[k * KDIM + j0 + j];
        }
        __syncthreads();
        #pragma unroll
        for (int j = 0; j < KT; j++) {
            float2 xv = *reinterpret_cast<const float2*>(&Xs[j * 128 + 2 * ng]);
            ull xx = pk2(xv.x, xv.x);
            ull yy = pk2(xv.y, xv.y);
            #pragma unroll
            for (int cp = 0; cp < OPT / 2; cp++) {
                ull m2 = *reinterpret_cast<const ull*>(&Ms[j * KOUT + og * OPT + 2 * cp]);
                fma2(acc0[cp], xx, m2);
                fma2(acc1[cp], yy, m2);
            }
        }
        __syncthreads();
    }

    float r0[OPT], r1[OPT];
    #pragma unroll
    for (int cp = 0; cp < OPT / 2; cp++) {
        upk(acc0[cp], r0[2 * cp], r0[2 * cp + 1]);
        upk(acc1[cp], r1[2 * cp], r1[2 * cp + 1]);
    }
    #pragma unroll
    for (int cc = 0; cc < OPT; cc++) {
        float bias = __ldg(&c[og * OPT + cc]);
        r0[cc] += bias;
        r1[cc] += bias;
    }
    const int nA = n0 + 2 * ng, nB = nA + 1;
    if (nA < N) {
        #pragma unroll
        for (int v = 0; v < OPT / 4; v++)
            *reinterpret_cast<float4*>(&out[(size_t)nA * KOUT + og * OPT + 4 * v]) =
                make_float4(r0[4 * v], r0[4 * v + 1], r0[4 * v + 2], r0[4 * v + 3]);
    }
    if (nB < N) {
        #pragma unroll
        for (int v = 0; v < OPT / 4; v++)
            *reinterpret_cast<float4*>(&out[(size_t)nB * KOUT + og * OPT + 4 * v]) =
                make_float4(r1[4 * v], r1[4 * v + 1], r1[4 * v + 2], r1[4 * v + 3]);
    }
}

__global__ void __launch_bounds__(256)
node_kernel(const float* __restrict__ xp, const float* __restrict__ xa,
            const float* __restrict__ Mp, const float* __restrict__ cp,
            const float* __restrict__ Ma, const float* __restrict__ ca,
            float* __restrict__ pL, float* __restrict__ aL,
            int Np, int Na, int npBlocks) {
    __shared__ float Xs[32 * 128];
    __shared__ float Ms[32 * 48];
    if ((int)blockIdx.x < npBlocks)
        node_body<256, 48, 12>(xp, Mp, cp, pL, Np, blockIdx.x, Xs, Ms);
    else
        node_body<128, 16, 4>(xa, Ma, ca, aL, Na, blockIdx.x - npBlocks, Xs, Ms);
}

// ---------------------------------------------------------------------------
// Kernel 3 (fused, merged edge types): A in regs (4 cols/lane), broadcast
// LDS, streaming STG.128, (256,2). 3-stage pipeline per iteration:
//   softmax(batch t+1) -> bsh[buf^1]   (independent of stage 3 -> interleaved)
//   issue gathers for batch t+2 -> lg
//   epilogue FMA + stores for batch t from bsh[buf]
// ---------------------------------------------------------------------------
__global__ void __launch_bounds__(256, 2)
edge_fused_kernel(const int* __restrict__ eiW, const int* __restrict__ eiC,
                  int E,
                  const float* __restrict__ aL, const float* __restrict__ pL,
                  const float* __restrict__ A_w, const float* __restrict__ A_c,
                  float* __restrict__ out, int nbHalf) {
    __shared__ __align__(16) float2 bsh[8][2][4][32];   // [warp][buf][pair][{b,b}x16]

    const bool isW = (int)blockIdx.x < nbHalf;
    const int bid = isW ? blockIdx.x : blockIdx.x - nbHalf;
    const int* ei = isW ? eiW : eiC;
    const float* srcL = isW ? aL : (pL + 16);
    const int sStride = isW ? 16 : 48;
    const float* dstL = isW ? pL : (pL + 32);
    const float* A = isW ? A_w : A_c;
    float* o = isW ? out : out + (size_t)E * 128;

    const int lane = threadIdx.x & 31;
    const int w = threadIdx.x >> 5;
    const int k16 = lane & 15;
    const int half = lane >> 4;

    // A preload: lane owns output columns [4*lane, 4*lane+4) for all 16 k.
    ull aLr[16], aHr[16];
    #pragma unroll
    for (int k = 0; k < 16; k++) {
        float4 v = reinterpret_cast<const float4*>(A)[k * 32 + lane];
        aLr[k] = pk2(v.x, v.y);
        aHr[k] = pk2(v.z, v.w);
    }

    const int pairs = E >> 1;              // E even
    const int gw = bid * 8 + w;
    const int base = gw * 4;
    const int step = nbHalf * 8 * 4;       // pairs consumed per iter, all warps
    if (base >= pairs) return;
    const int nIter = (pairs - base + step - 1) / step;

    float lg[4];

    // gather + leaky-relu logits for batch t (clamped; safe for any t)
    #define GATHER(t_)                                                        \
        do {                                                                  \
            int pb_ = base + (t_) * step;                                     \
            _Pragma("unroll")                                                 \
            for (int u = 0; u < 4; u++) {                                     \
                int e_ = min(2 * (pb_ + u) + half, E - 1);                    \
                int s_ = __ldg(&ei[e_]);                                      \
                int d_ = __ldg(&ei[E + e_]);                                  \
                float l_ = __ldg(&srcL[(size_t)s_ * sStride + k16]) +         \
                           __ldg(&dstL[(size_t)d_ * 48 + k16]);               \
                lg[u] = fmaxf(l_, 0.01f * l_);                                \
            }                                                                 \
        } while (0)

    // no-max softmax (logits bounded; fp32 headroom is huge) -> bsh[w][buf_]
    #define SOFTMAX_TO(buf_)                                                  \
        do {                                                                  \
            float ex_[4], sm_[4];                                             \
            _Pragma("unroll")                                                 \
            for (int u = 0; u < 4; u++) {                                     \
                ex_[u] = __expf(lg[u]);                                       \
                sm_[u] = ex_[u];                                              \
            }                                                                 \
            _Pragma("unroll")                                                 \
            for (int m = 8; m; m >>= 1) {                                     \
                _Pragma("unroll")                                             \
                for (int u = 0; u < 4; u++)                                   \
                    sm_[u] += __shfl_xor_sync(0xffffffffu, sm_[u], m, 16);    \
            }                                                                 \
            _Pragma("unroll")                                                 \
            for (int u = 0; u < 4; u++) {                                     \
                float b_ = __fdividef(ex_[u], sm_[u]);                        \
                bsh[w][buf_][u][lane] = make_float2(b_, b_);                  \
            }                                                                 \
        } while (0)

    // prologue: batch 0 softmax into buf 0; issue batch-1 gathers
    GATHER(0);
    SOFTMAX_TO(0);
    GATHER(1);
    __syncwarp();

    for (int t = 0; t < nIter; t++) {
        const int buf = t & 1;

        // stage 1: softmax batch t+1 (gathers issued last iter) -> buf^1
        SOFTMAX_TO(buf ^ 1);
        // stage 2: issue gathers batch t+2 (fly under the FMA burst)
        GATHER(t + 2);

        // stage 3: epilogue batch t from bsh[buf]
        const int pb = base + t * step;
        #pragma unroll
        for (int u = 0; u < 4; u++) {
            if (pb + u < pairs) {
                #pragma unroll
                for (int h = 0; h < 2; h++) {
                    const ulonglong2* bq =
                        reinterpret_cast<const ulonglong2*>(&bsh[w][buf][u][16 * h]);
                    ull accL = 0ull, accH = 0ull;
                    #pragma unroll
                    for (int k2 = 0; k2 < 8; k2++) {
                        ulonglong2 q = bq[k2];
                        fma2(accL, q.x, aLr[2 * k2]);
                        fma2(accH, q.x, aHr[2 * k2]);
                        fma2(accL, q.y, aLr[2 * k2 + 1]);
                        fma2(accH, q.y, aHr[2 * k2 + 1]);
                    }
                    st4cs(o + (size_t)(2 * (pb + u) + h) * 128 + 4 * lane,
                          accL, accH);
                }
            }
        }
        __syncwarp();
    }
    #undef GATHER
    #undef SOFTMAX_TO
}

// ---------------------------------------------------------------------------
extern "C" void kernel_launch(void* const* d_in, const int* in_sizes, int n_in,
                              void* d_out, int out_size) {
    const float* x_paper   = (const float*)d_in[0];
    const float* x_author  = (const float*)d_in[1];
    const float* Wp_paper  = (const float*)d_in[2];
    const float* bp_paper  = (const float*)d_in[3];
    const float* Wp_author = (const float*)d_in[4];
    const float* bp_author = (const float*)d_in[5];
    const float* Ws_writes = (const float*)d_in[6];
    const float* bs_writes = (const float*)d_in[7];
    const float* A_writes  = (const float*)d_in[8];
    const float* Ws_cites  = (const float*)d_in[9];
    const float* bs_cites  = (const float*)d_in[10];
    const float* A_cites   = (const float*)d_in[11];
    const int*   ei_writes = (const int*)d_in[12];
    const int*   ei_cites  = (const int*)d_in[13];
    float* out = (float*)d_out;

    const int Np = in_sizes[0] / 256;
    const int Na = in_sizes[1] / 128;
    const int E  = in_sizes[12] / 2;

    float *fold, *pL, *aL;
    cudaGetSymbolAddress((void**)&fold, g_fold);
    cudaGetSymbolAddress((void**)&pL, g_paperL);
    cudaGetSymbolAddress((void**)&aL, g_authorL);
    float* Mp = fold;
    float* Ma = fold + 12288;
    float* cp = fold + 14336;
    float* ca = fold + 14384;

    cudaMemsetAsync(fold, 0, 14400 * sizeof(float));

    fold_kernel<<<dim3(64, 4), 256>>>(Wp_paper, bp_paper, Wp_author, bp_author,
                                      Ws_writes, bs_writes, Ws_cites, bs_cites);

    const int npB = (Np + 127) / 128;
    const int naB = (Na + 127) / 128;
    node_kernel<<<npB + naB, 256>>>(x_paper, x_author, Mp, cp, Ma, ca,
                                    pL, aL, Np, Na, npB);

    const int nbHalf = 148;  // persistent single wave: 2 CTAs/SM
    edge_fused_kernel<<<2 * nbHalf, 256>>>(ei_writes, ei_cites, E, aL, pL,
                                           A_writes, A_cites, out, nbHalf);
}